// round 2
// baseline (speedup 1.0000x reference)
#include <cuda_runtime.h>

#define N_NODES 50000
#define N_EDGES 640000
#define HID 128
#define BM 64           // rows per MLP block
#define P  132          // padded smem row stride (floats) for z / h1 tiles

// scratch (static __device__ — no allocations allowed). float4 => 16B aligned.
__device__ float4 g_aggr4[(size_t)N_NODES * (HID / 4)];
__device__ float4 g_proj4[16 * (HID / 4)];
__device__ int    g_idx64;   // 1 if edge_index/edge_attr are int64, 0 if int32

// ---------------------------------------------------------------------------
// Kernel 0: dtype probe. For int64 indices < 2^31 every odd 32-bit word is 0.
// ---------------------------------------------------------------------------
__global__ void detect_kernel(const unsigned* __restrict__ ei_raw) {
    unsigned acc = 0;
#pragma unroll
    for (int i = 0; i < 128; i++) acc |= ei_raw[2 * i + 1];
    g_idx64 = (acc == 0u) ? 1 : 0;
}

// ---------------------------------------------------------------------------
// Kernel 1: proj[16][128] = emb @ We + be   (tiny)
// ---------------------------------------------------------------------------
__global__ void proj_kernel(const float* __restrict__ emb,
                            const float* __restrict__ We,
                            const float* __restrict__ be) {
    int tid = blockIdx.x * blockDim.x + threadIdx.x;
    if (tid >= 16 * HID) return;
    int t = tid >> 7;
    int j = tid & 127;
    float s = be[j];
#pragma unroll
    for (int d = 0; d < 8; d++)
        s = fmaf(emb[t * 8 + d], We[d * HID + j], s);
    ((float*)g_proj4)[tid] = s;
}

// ---------------------------------------------------------------------------
// Kernel 2: zero the aggregation buffer (float4)
// ---------------------------------------------------------------------------
__global__ void zero_kernel() {
    int tid = blockIdx.x * blockDim.x + threadIdx.x;  // 1,600,000 float4 exactly
    g_aggr4[tid] = make_float4(0.f, 0.f, 0.f, 0.f);
}

// ---------------------------------------------------------------------------
// Kernel 3: edge scatter. One warp per edge; lane handles a float4.
// msg = relu(x[src] + proj[h]); red.v4 into g_aggr[dst].
// Index dtype (int32 vs int64) resolved at runtime via g_idx64.
// ---------------------------------------------------------------------------
__global__ void edge_kernel(const float4* __restrict__ x4,
                            const void* __restrict__ ei_v,
                            const void* __restrict__ ea_v) {
    int warp = (blockIdx.x * blockDim.x + threadIdx.x) >> 5;
    int lane = threadIdx.x & 31;
    if (warp >= N_EDGES) return;

    long long src, dst, a0, a1, a2;
    if (g_idx64) {
        const long long* ei = (const long long*)ei_v;
        const long long* ea = (const long long*)ea_v;
        src = ei[warp];
        dst = ei[N_EDGES + warp];
        a0 = ea[3LL * warp + 0];
        a1 = ea[3LL * warp + 1];
        a2 = ea[3LL * warp + 2];
    } else {
        const int* ei = (const int*)ei_v;
        const int* ea = (const int*)ea_v;
        src = ei[warp];
        dst = ei[N_EDGES + warp];
        a0 = ea[3 * warp + 0];
        a1 = ea[3 * warp + 1];
        a2 = ea[3 * warp + 2];
    }
    int h = (int)((a0 + 3 * a1 + 7 * a2) & 15);   // values >=0, %16 == &15

    float4 xv = x4[(size_t)src * 32 + lane];
    float4 pv = g_proj4[h * 32 + lane];
    float4 m;
    m.x = fmaxf(xv.x + pv.x, 0.f);
    m.y = fmaxf(xv.y + pv.y, 0.f);
    m.z = fmaxf(xv.z + pv.z, 0.f);
    m.w = fmaxf(xv.w + pv.w, 0.f);

    float4* a = &g_aggr4[(size_t)dst * 32 + lane];
    asm volatile("red.global.add.v4.f32 [%0], {%1, %2, %3, %4};"
                 :: "l"(a), "f"(m.x), "f"(m.y), "f"(m.z), "f"(m.w)
                 : "memory");
}

// ---------------------------------------------------------------------------
// Kernel 4: fused MLP.  z = (1+eps)*x + aggr; out = relu(z@W1+b1)@W2 + b2.
// Block: 64 rows, 256 threads, 4x8 register tile. W1/W2 resident in smem.
// ---------------------------------------------------------------------------
__device__ __forceinline__ void tile_gemm(const float* __restrict__ zsm,
                                          const float* __restrict__ wsm,
                                          int r0, int c0, float acc[4][8]) {
#pragma unroll 4
    for (int k = 0; k < HID; k++) {
        float zr[4];
#pragma unroll
        for (int i = 0; i < 4; i++) zr[i] = zsm[(r0 + i) * P + k];
        float4 wa = *(const float4*)&wsm[k * HID + c0];
        float4 wb = *(const float4*)&wsm[k * HID + c0 + 4];
        float w[8] = {wa.x, wa.y, wa.z, wa.w, wb.x, wb.y, wb.z, wb.w};
#pragma unroll
        for (int i = 0; i < 4; i++)
#pragma unroll
            for (int j = 0; j < 8; j++)
                acc[i][j] = fmaf(zr[i], w[j], acc[i][j]);
    }
}

__global__ void __launch_bounds__(256, 1)
mlp_kernel(const float* __restrict__ x,
           const float* __restrict__ W1, const float* __restrict__ b1,
           const float* __restrict__ W2, const float* __restrict__ b2,
           const float* __restrict__ epsp,
           float* __restrict__ out) {
    extern __shared__ float sm[];
    float* zs  = sm;                 // BM*P
    float* h1s = zs + BM * P;        // BM*P
    float* w1s = h1s + BM * P;       // 128*128
    float* w2s = w1s + HID * HID;    // 128*128

    const int tid  = threadIdx.x;
    const int base = blockIdx.x * BM;
    const float eps1 = 1.0f + *epsp;

    // load weights (coalesced float4)
    const float4* W14 = (const float4*)W1;
    const float4* W24 = (const float4*)W2;
#pragma unroll
    for (int it = 0; it < 16; it++) {
        int i = tid + it * 256;          // 4096 float4 each
        ((float4*)w1s)[i] = W14[i];
        ((float4*)w2s)[i] = W24[i];
    }

    // build z tile: z = (1+eps)*x + aggr
    const float4* x4 = (const float4*)x;
#pragma unroll
    for (int it = 0; it < 8; it++) {
        int idx = tid + it * 256;        // 0..2047 float4 (64 rows x 32)
        int row = idx >> 5;
        int c4  = idx & 31;
        int g   = base + row;
        float4 v = make_float4(0.f, 0.f, 0.f, 0.f);
        if (g < N_NODES) {
            float4 xv = x4[(size_t)g * 32 + c4];
            float4 av = g_aggr4[(size_t)g * 32 + c4];
            v.x = fmaf(eps1, xv.x, av.x);
            v.y = fmaf(eps1, xv.y, av.y);
            v.z = fmaf(eps1, xv.z, av.z);
            v.w = fmaf(eps1, xv.w, av.w);
        }
        *(float4*)&zs[row * P + c4 * 4] = v;
    }
    __syncthreads();

    const int ty = tid >> 4, tx = tid & 15;
    const int r0 = ty * 4, c0 = tx * 8;

    // GEMM1: h1 = relu(z @ W1 + b1)
    float acc[4][8];
#pragma unroll
    for (int j = 0; j < 8; j++) {
        float bb = b1[c0 + j];
#pragma unroll
        for (int i = 0; i < 4; i++) acc[i][j] = bb;
    }
    tile_gemm(zs, w1s, r0, c0, acc);

#pragma unroll
    for (int i = 0; i < 4; i++) {
        float4 pa, pb;
        pa.x = fmaxf(acc[i][0], 0.f); pa.y = fmaxf(acc[i][1], 0.f);
        pa.z = fmaxf(acc[i][2], 0.f); pa.w = fmaxf(acc[i][3], 0.f);
        pb.x = fmaxf(acc[i][4], 0.f); pb.y = fmaxf(acc[i][5], 0.f);
        pb.z = fmaxf(acc[i][6], 0.f); pb.w = fmaxf(acc[i][7], 0.f);
        *(float4*)&h1s[(r0 + i) * P + c0]     = pa;
        *(float4*)&h1s[(r0 + i) * P + c0 + 4] = pb;
    }
    __syncthreads();

    // GEMM2: out = h1 @ W2 + b2
#pragma unroll
    for (int j = 0; j < 8; j++) {
        float bb = b2[c0 + j];
#pragma unroll
        for (int i = 0; i < 4; i++) acc[i][j] = bb;
    }
    tile_gemm(h1s, w2s, r0, c0, acc);

#pragma unroll
    for (int i = 0; i < 4; i++) {
        int g = base + r0 + i;
        if (g < N_NODES) {
            float4 pa = make_float4(acc[i][0], acc[i][1], acc[i][2], acc[i][3]);
            float4 pb = make_float4(acc[i][4], acc[i][5], acc[i][6], acc[i][7]);
            *(float4*)&out[(size_t)g * HID + c0]     = pa;
            *(float4*)&out[(size_t)g * HID + c0 + 4] = pb;
        }
    }
}

// ---------------------------------------------------------------------------
extern "C" void kernel_launch(void* const* d_in, const int* in_sizes, int n_in,
                              void* d_out, int out_size) {
    const float* x   = (const float*)d_in[0];
    const void*  ei  = d_in[1];
    const void*  ea  = d_in[2];
    const float* emb = (const float*)d_in[3];
    const float* We  = (const float*)d_in[4];
    const float* be  = (const float*)d_in[5];
    const float* W1  = (const float*)d_in[6];
    const float* b1  = (const float*)d_in[7];
    const float* W2  = (const float*)d_in[8];
    const float* b2  = (const float*)d_in[9];
    const float* eps = (const float*)d_in[10];
    float*       out = (float*)d_out;

    const size_t smem_bytes = (2 * BM * P + 2 * HID * HID) * sizeof(float); // ~194 KB
    cudaFuncSetAttribute(mlp_kernel, cudaFuncAttributeMaxDynamicSharedMemorySize,
                         (int)smem_bytes);

    detect_kernel<<<1, 1>>>((const unsigned*)ei);
    proj_kernel<<<8, 256>>>(emb, We, be);
    zero_kernel<<<(N_NODES * HID / 4) / 256, 256>>>();                 // 6250 blocks
    edge_kernel<<<N_EDGES / 8, 256>>>((const float4*)x, ei, ea);       // 80000 blocks
    mlp_kernel<<<(N_NODES + BM - 1) / BM, 256, smem_bytes>>>(x, W1, b1, W2, b2, eps, out);
}

// round 3
// speedup vs baseline: 1.0081x; 1.0081x over previous
#include <cuda_runtime.h>

#define N_NODES 50000
#define N_EDGES 640000
#define HID 128
#define BM 64           // rows per MLP block
#define P  132          // padded smem row stride (floats) for z / h1 tiles

// scratch (static __device__ — no allocations allowed). float4 => 16B aligned.
__device__ float4 g_aggr4[(size_t)N_NODES * (HID / 4)];
__device__ float4 g_proj4[16 * (HID / 4)];
__device__ int    g_idx64;   // 1 if edge_index/edge_attr are int64, 0 if int32

typedef unsigned long long ull;

// ---- packed f32x2 helpers (sm_103a FFMA2 — only reachable via PTX) --------
__device__ __forceinline__ ull pack2(float lo, float hi) {
    ull r;
    asm("mov.b64 %0, {%1, %2};" : "=l"(r) : "f"(lo), "f"(hi));
    return r;
}
__device__ __forceinline__ void unpack2(ull v, float& lo, float& hi) {
    asm("mov.b64 {%0, %1}, %2;" : "=f"(lo), "=f"(hi) : "l"(v));
}
__device__ __forceinline__ void fma2(ull& d, ull a, ull b) {
    asm("fma.rn.f32x2 %0, %1, %2, %0;" : "+l"(d) : "l"(a), "l"(b));
}

// ---------------------------------------------------------------------------
// Kernel 0: dtype probe. For int64 indices < 2^31 every odd 32-bit word is 0.
// ---------------------------------------------------------------------------
__global__ void detect_kernel(const unsigned* __restrict__ ei_raw) {
    unsigned acc = 0;
#pragma unroll
    for (int i = 0; i < 128; i++) acc |= ei_raw[2 * i + 1];
    g_idx64 = (acc == 0u) ? 1 : 0;
}

// ---------------------------------------------------------------------------
// Kernel 1: proj[16][128] = emb @ We + be   (tiny)
// ---------------------------------------------------------------------------
__global__ void proj_kernel(const float* __restrict__ emb,
                            const float* __restrict__ We,
                            const float* __restrict__ be) {
    int tid = blockIdx.x * blockDim.x + threadIdx.x;
    if (tid >= 16 * HID) return;
    int t = tid >> 7;
    int j = tid & 127;
    float s = be[j];
#pragma unroll
    for (int d = 0; d < 8; d++)
        s = fmaf(emb[t * 8 + d], We[d * HID + j], s);
    ((float*)g_proj4)[tid] = s;
}

// ---------------------------------------------------------------------------
// Kernel 2: zero the aggregation buffer (float4)
// ---------------------------------------------------------------------------
__global__ void zero_kernel() {
    int tid = blockIdx.x * blockDim.x + threadIdx.x;  // 1,600,000 float4 exactly
    g_aggr4[tid] = make_float4(0.f, 0.f, 0.f, 0.f);
}

// ---------------------------------------------------------------------------
// Kernel 3: edge scatter. One warp per edge; lane handles a float4.
// ---------------------------------------------------------------------------
__global__ void edge_kernel(const float4* __restrict__ x4,
                            const void* __restrict__ ei_v,
                            const void* __restrict__ ea_v) {
    int warp = (blockIdx.x * blockDim.x + threadIdx.x) >> 5;
    int lane = threadIdx.x & 31;
    if (warp >= N_EDGES) return;

    long long src, dst, a0, a1, a2;
    if (g_idx64) {
        const long long* ei = (const long long*)ei_v;
        const long long* ea = (const long long*)ea_v;
        src = ei[warp];
        dst = ei[N_EDGES + warp];
        a0 = ea[3LL * warp + 0];
        a1 = ea[3LL * warp + 1];
        a2 = ea[3LL * warp + 2];
    } else {
        const int* ei = (const int*)ei_v;
        const int* ea = (const int*)ea_v;
        src = ei[warp];
        dst = ei[N_EDGES + warp];
        a0 = ea[3 * warp + 0];
        a1 = ea[3 * warp + 1];
        a2 = ea[3 * warp + 2];
    }
    int h = (int)((a0 + 3 * a1 + 7 * a2) & 15);

    float4 xv = x4[(size_t)src * 32 + lane];
    float4 pv = g_proj4[h * 32 + lane];
    float4 m;
    m.x = fmaxf(xv.x + pv.x, 0.f);
    m.y = fmaxf(xv.y + pv.y, 0.f);
    m.z = fmaxf(xv.z + pv.z, 0.f);
    m.w = fmaxf(xv.w + pv.w, 0.f);

    float4* a = &g_aggr4[(size_t)dst * 32 + lane];
    asm volatile("red.global.add.v4.f32 [%0], {%1, %2, %3, %4};"
                 :: "l"(a), "f"(m.x), "f"(m.y), "f"(m.z), "f"(m.w)
                 : "memory");
}

// ---------------------------------------------------------------------------
// Kernel 4: fused MLP with packed fp32x2 FMA.
// z = (1+eps)*x + aggr; out = relu(z@W1+b1)@W2 + b2.
// 64 rows/block, 256 threads, each thread: 4 rows x 4 column-PAIRS (8 cols).
// Weight pairs come free from float4 smem loads reinterpreted as 2x f32x2.
// ---------------------------------------------------------------------------
__device__ __forceinline__ void tile_gemm2(const float* __restrict__ zsm,
                                           const float* __restrict__ wsm,
                                           int r0, int c0, ull acc[4][4]) {
#pragma unroll 4
    for (int k = 0; k < HID; k++) {
        ull z2[4];
#pragma unroll
        for (int i = 0; i < 4; i++) {
            float zv = zsm[(r0 + i) * P + k];
            z2[i] = pack2(zv, zv);
        }
        // two float4 loads = 4 f32x2 weight pairs {c, c+1}
        ulonglong2 wa = *(const ulonglong2*)&wsm[k * HID + c0];
        ulonglong2 wb = *(const ulonglong2*)&wsm[k * HID + c0 + 4];
        ull w2[4] = {wa.x, wa.y, wb.x, wb.y};
#pragma unroll
        for (int i = 0; i < 4; i++)
#pragma unroll
            for (int p = 0; p < 4; p++)
                fma2(acc[i][p], z2[i], w2[p]);
    }
}

__global__ void __launch_bounds__(256, 1)
mlp_kernel(const float* __restrict__ x,
           const float* __restrict__ W1, const float* __restrict__ b1,
           const float* __restrict__ W2, const float* __restrict__ b2,
           const float* __restrict__ epsp,
           float* __restrict__ out) {
    extern __shared__ float sm[];
    float* zs  = sm;                 // BM*P (doubles as h1 tile after GEMM1)
    float* w1s = zs + BM * P;        // 128*128
    float* w2s = w1s + HID * HID;    // 128*128

    const int tid  = threadIdx.x;
    const int base = blockIdx.x * BM;
    const float eps1 = 1.0f + *epsp;

    // load weights (coalesced float4)
    const float4* W14 = (const float4*)W1;
    const float4* W24 = (const float4*)W2;
#pragma unroll
    for (int it = 0; it < 16; it++) {
        int i = tid + it * 256;          // 4096 float4 each
        ((float4*)w1s)[i] = W14[i];
        ((float4*)w2s)[i] = W24[i];
    }

    // build z tile: z = (1+eps)*x + aggr
    const float4* x4 = (const float4*)x;
#pragma unroll
    for (int it = 0; it < 8; it++) {
        int idx = tid + it * 256;        // 0..2047 float4 (64 rows x 32)
        int row = idx >> 5;
        int c4  = idx & 31;
        int g   = base + row;
        float4 v = make_float4(0.f, 0.f, 0.f, 0.f);
        if (g < N_NODES) {
            float4 xv = x4[(size_t)g * 32 + c4];
            float4 av = g_aggr4[(size_t)g * 32 + c4];
            v.x = fmaf(eps1, xv.x, av.x);
            v.y = fmaf(eps1, xv.y, av.y);
            v.z = fmaf(eps1, xv.z, av.z);
            v.w = fmaf(eps1, xv.w, av.w);
        }
        *(float4*)&zs[row * P + c4 * 4] = v;
    }
    __syncthreads();

    const int ty = tid >> 4, tx = tid & 15;
    const int r0 = ty * 4, c0 = tx * 8;

    // GEMM1: h1 = relu(z @ W1 + b1)
    ull acc[4][4];
#pragma unroll
    for (int p = 0; p < 4; p++) {
        ull bb = pack2(b1[c0 + 2 * p], b1[c0 + 2 * p + 1]);
#pragma unroll
        for (int i = 0; i < 4; i++) acc[i][p] = bb;
    }
    tile_gemm2(zs, w1s, r0, c0, acc);

    // relu + stage h1 into registers, then overwrite zs after sync
    float4 h1a[4], h1b[4];
#pragma unroll
    for (int i = 0; i < 4; i++) {
        float v0, v1, v2, v3, v4, v5, v6, v7;
        unpack2(acc[i][0], v0, v1);
        unpack2(acc[i][1], v2, v3);
        unpack2(acc[i][2], v4, v5);
        unpack2(acc[i][3], v6, v7);
        h1a[i] = make_float4(fmaxf(v0, 0.f), fmaxf(v1, 0.f),
                             fmaxf(v2, 0.f), fmaxf(v3, 0.f));
        h1b[i] = make_float4(fmaxf(v4, 0.f), fmaxf(v5, 0.f),
                             fmaxf(v6, 0.f), fmaxf(v7, 0.f));
    }
    __syncthreads();   // everyone done reading zs
#pragma unroll
    for (int i = 0; i < 4; i++) {
        *(float4*)&zs[(r0 + i) * P + c0]     = h1a[i];
        *(float4*)&zs[(r0 + i) * P + c0 + 4] = h1b[i];
    }
    __syncthreads();

    // GEMM2: out = h1 @ W2 + b2
#pragma unroll
    for (int p = 0; p < 4; p++) {
        ull bb = pack2(b2[c0 + 2 * p], b2[c0 + 2 * p + 1]);
#pragma unroll
        for (int i = 0; i < 4; i++) acc[i][p] = bb;
    }
    tile_gemm2(zs, w2s, r0, c0, acc);

#pragma unroll
    for (int i = 0; i < 4; i++) {
        int g = base + r0 + i;
        if (g < N_NODES) {
            float v0, v1, v2, v3, v4, v5, v6, v7;
            unpack2(acc[i][0], v0, v1);
            unpack2(acc[i][1], v2, v3);
            unpack2(acc[i][2], v4, v5);
            unpack2(acc[i][3], v6, v7);
            *(float4*)&out[(size_t)g * HID + c0]     = make_float4(v0, v1, v2, v3);
            *(float4*)&out[(size_t)g * HID + c0 + 4] = make_float4(v4, v5, v6, v7);
        }
    }
}

// ---------------------------------------------------------------------------
extern "C" void kernel_launch(void* const* d_in, const int* in_sizes, int n_in,
                              void* d_out, int out_size) {
    const float* x   = (const float*)d_in[0];
    const void*  ei  = d_in[1];
    const void*  ea  = d_in[2];
    const float* emb = (const float*)d_in[3];
    const float* We  = (const float*)d_in[4];
    const float* be  = (const float*)d_in[5];
    const float* W1  = (const float*)d_in[6];
    const float* b1  = (const float*)d_in[7];
    const float* W2  = (const float*)d_in[8];
    const float* b2  = (const float*)d_in[9];
    const float* eps = (const float*)d_in[10];
    float*       out = (float*)d_out;

    const size_t smem_bytes = (BM * P + 2 * HID * HID) * sizeof(float); // ~165 KB
    cudaFuncSetAttribute(mlp_kernel, cudaFuncAttributeMaxDynamicSharedMemorySize,
                         (int)smem_bytes);

    detect_kernel<<<1, 1>>>((const unsigned*)ei);
    proj_kernel<<<8, 256>>>(emb, We, be);
    zero_kernel<<<(N_NODES * HID / 4) / 256, 256>>>();                 // 6250 blocks
    edge_kernel<<<N_EDGES / 8, 256>>>((const float4*)x, ei, ea);       // 80000 blocks
    mlp_kernel<<<(N_NODES + BM - 1) / BM, 256, smem_bytes>>>(x, W1, b1, W2, b2, eps, out);
}

// round 5
// speedup vs baseline: 1.6100x; 1.5970x over previous
#include <cuda_runtime.h>
#include <cuda_bf16.h>
#include <cstdint>

#define N_NODES 50000
#define N_EDGES 640000
#define HID 128
#define KSTR 136                     // padded k-stride (bf16 elems)
#define KSTRB (KSTR * 2)             // 272 bytes
#define TILE_B (128 * KSTRB)         // 34816 bytes per bf16 tile

// ---------------- scratch (static __device__; no allocations) --------------
__device__ float4 g_aggr4[(size_t)N_NODES * (HID / 4)];
__device__ float4 g_proj4[16 * (HID / 4)];
__device__ int    g_idx64;
// bf16 hi/lo weight tiles, transposed [n][k], stride KSTR
__device__ __align__(16) unsigned short g_w1h[128 * KSTR];
__device__ __align__(16) unsigned short g_w1l[128 * KSTR];
__device__ __align__(16) unsigned short g_w2h[128 * KSTR];
__device__ __align__(16) unsigned short g_w2l[128 * KSTR];

// ---------------- helpers ---------------------------------------------------
__device__ __forceinline__ uint32_t smem_u32(const void* p) {
    uint32_t a;
    asm("{ .reg .u64 t; cvta.to.shared.u64 t, %1; cvt.u32.u64 %0, t; }"
        : "=r"(a) : "l"(p));
    return a;
}
__device__ __forceinline__ void ldsm4(uint32_t* r, uint32_t a) {
    asm volatile("ldmatrix.sync.aligned.m8n8.x4.shared.b16 {%0,%1,%2,%3}, [%4];"
                 : "=r"(r[0]), "=r"(r[1]), "=r"(r[2]), "=r"(r[3]) : "r"(a));
}
__device__ __forceinline__ void mma_bf16(float* d, const uint32_t* a,
                                         uint32_t b0, uint32_t b1) {
    asm volatile(
        "mma.sync.aligned.m16n8k16.row.col.f32.bf16.bf16.f32 "
        "{%0,%1,%2,%3}, {%4,%5,%6,%7}, {%8,%9}, {%0,%1,%2,%3};"
        : "+f"(d[0]), "+f"(d[1]), "+f"(d[2]), "+f"(d[3])
        : "r"(a[0]), "r"(a[1]), "r"(a[2]), "r"(a[3]), "r"(b0), "r"(b1));
}
__device__ __forceinline__ uint32_t splitpair(float v0, float v1, uint32_t& lo) {
    __nv_bfloat16 h0 = __float2bfloat16(v0), h1 = __float2bfloat16(v1);
    __nv_bfloat16 l0 = __float2bfloat16(v0 - __bfloat162float(h0));
    __nv_bfloat16 l1 = __float2bfloat16(v1 - __bfloat162float(h1));
    lo = (uint32_t)__bfloat16_as_ushort(l0) |
         ((uint32_t)__bfloat16_as_ushort(l1) << 16);
    return (uint32_t)__bfloat16_as_ushort(h0) |
           ((uint32_t)__bfloat16_as_ushort(h1) << 16);
}

// ---------------------------------------------------------------------------
// small kernels
// ---------------------------------------------------------------------------
__global__ void detect_kernel(const unsigned* __restrict__ ei_raw) {
    unsigned acc = 0;
#pragma unroll
    for (int i = 0; i < 128; i++) acc |= ei_raw[2 * i + 1];
    g_idx64 = (acc == 0u) ? 1 : 0;
}

__global__ void proj_kernel(const float* __restrict__ emb,
                            const float* __restrict__ We,
                            const float* __restrict__ be) {
    int tid = blockIdx.x * blockDim.x + threadIdx.x;
    if (tid >= 16 * HID) return;
    int t = tid >> 7, j = tid & 127;
    float s = be[j];
#pragma unroll
    for (int d = 0; d < 8; d++)
        s = fmaf(emb[t * 8 + d], We[d * HID + j], s);
    ((float*)g_proj4)[tid] = s;
}

// split W into bf16 hi/lo, transposed to [n][k], stride KSTR (pad zeroed)
__global__ void wsplit_kernel(const float* __restrict__ W1,
                              const float* __restrict__ W2) {
    int tid = blockIdx.x * blockDim.x + threadIdx.x;  // 2*128*KSTR = 34816
    if (tid >= 2 * 128 * KSTR) return;
    int mat = tid / (128 * KSTR);
    int rem = tid % (128 * KSTR);
    int n = rem / KSTR;
    int k = rem % KSTR;
    unsigned short hv = 0, lv = 0;
    if (k < 128) {
        const float* W = mat ? W2 : W1;
        float w = W[k * HID + n];                 // Wt[n][k] = W[k][n]
        __nv_bfloat16 h = __float2bfloat16(w);
        __nv_bfloat16 l = __float2bfloat16(w - __bfloat162float(h));
        hv = __bfloat16_as_ushort(h);
        lv = __bfloat16_as_ushort(l);
    }
    (mat ? g_w2h : g_w1h)[n * KSTR + k] = hv;
    (mat ? g_w2l : g_w1l)[n * KSTR + k] = lv;
}

// init aggr = (1+eps)*x  (edge reds accumulate on top)
__global__ void init_kernel(const float4* __restrict__ x4,
                            const float* __restrict__ epsp) {
    int tid = blockIdx.x * blockDim.x + threadIdx.x;  // 1,600,000 exactly
    float e1 = 1.0f + *epsp;
    float4 v = x4[tid];
    v.x *= e1; v.y *= e1; v.z *= e1; v.w *= e1;
    g_aggr4[tid] = v;
}

__global__ void edge_kernel(const float4* __restrict__ x4,
                            const void* __restrict__ ei_v,
                            const void* __restrict__ ea_v) {
    int warp = (blockIdx.x * blockDim.x + threadIdx.x) >> 5;
    int lane = threadIdx.x & 31;
    if (warp >= N_EDGES) return;

    long long src, dst, a0, a1, a2;
    if (g_idx64) {
        const long long* ei = (const long long*)ei_v;
        const long long* ea = (const long long*)ea_v;
        src = ei[warp]; dst = ei[N_EDGES + warp];
        a0 = ea[3LL * warp]; a1 = ea[3LL * warp + 1]; a2 = ea[3LL * warp + 2];
    } else {
        const int* ei = (const int*)ei_v;
        const int* ea = (const int*)ea_v;
        src = ei[warp]; dst = ei[N_EDGES + warp];
        a0 = ea[3 * warp]; a1 = ea[3 * warp + 1]; a2 = ea[3 * warp + 2];
    }
    int h = (int)((a0 + 3 * a1 + 7 * a2) & 15);

    float4 xv = x4[(size_t)src * 32 + lane];
    float4 pv = g_proj4[h * 32 + lane];
    float4 m;
    m.x = fmaxf(xv.x + pv.x, 0.f);
    m.y = fmaxf(xv.y + pv.y, 0.f);
    m.z = fmaxf(xv.z + pv.z, 0.f);
    m.w = fmaxf(xv.w + pv.w, 0.f);

    float4* a = &g_aggr4[(size_t)dst * 32 + lane];
    asm volatile("red.global.add.v4.f32 [%0], {%1, %2, %3, %4};"
                 :: "l"(a), "f"(m.x), "f"(m.y), "f"(m.z), "f"(m.w) : "memory");
}

// ---------------------------------------------------------------------------
// MLP via mma.sync bf16x3.  out = relu(z@W1+b1)@W2 + b2,  z = aggr (preadded)
// 128 rows/CTA, 8 warps, warp w owns rows 16w..16w+15 for BOTH gemms.
// ---------------------------------------------------------------------------
#define SM_B1  0
#define SM_B2  512
#define SM_ZH  1024
#define SM_ZL  (SM_ZH + TILE_B)
#define SM_W1H (SM_ZL + TILE_B)
#define SM_W1L (SM_W1H + TILE_B)
#define SM_W2H (SM_W1L + TILE_B)
#define SM_W2L (SM_W2H + TILE_B)
#define SM_TOT (SM_W2L + TILE_B)     // 209920 bytes

__device__ __forceinline__ void gemm128(uint32_t sb, uint32_t zh, uint32_t zl,
                                        uint32_t wh, uint32_t wl,
                                        uint32_t aByte, uint32_t bByte,
                                        float acc[16][4]) {
#pragma unroll
    for (int ks = 0; ks < 8; ks++) {
        uint32_t k0b = ks * 32;                   // 16 bf16 = 32B per k-step
        uint32_t ah[4], al[4];
        ldsm4(ah, sb + zh + aByte + k0b);
        ldsm4(al, sb + zl + aByte + k0b);
#pragma unroll
        for (int np = 0; np < 8; np++) {
            uint32_t wo = bByte + np * (16 * KSTRB) + k0b;
            uint32_t wH[4], wL[4];
            ldsm4(wH, sb + wh + wo);
            ldsm4(wL, sb + wl + wo);
            mma_bf16(acc[2 * np],     ah, wH[0], wH[1]);
            mma_bf16(acc[2 * np],     ah, wL[0], wL[1]);
            mma_bf16(acc[2 * np],     al, wH[0], wH[1]);
            mma_bf16(acc[2 * np + 1], ah, wH[2], wH[3]);
            mma_bf16(acc[2 * np + 1], ah, wL[2], wL[3]);
            mma_bf16(acc[2 * np + 1], al, wH[2], wH[3]);
        }
    }
}

__global__ void __launch_bounds__(256, 1)
mlp_mma_kernel(const float* __restrict__ b1, const float* __restrict__ b2,
               float* __restrict__ out) {
    extern __shared__ char smem[];
    const uint32_t sb = smem_u32(smem);
    const int tid = threadIdx.x, wid = tid >> 5, lane = tid & 31;
    const int base = blockIdx.x * 128;

    // biases
    if (tid < 128) {
        ((float*)(smem + SM_B1))[tid] = b1[tid];
        ((float*)(smem + SM_B2))[tid] = b2[tid];
    }

    // weight tiles: straight copies (2176 uint4 each)
    {
        const uint4* s[4] = {(const uint4*)g_w1h, (const uint4*)g_w1l,
                             (const uint4*)g_w2h, (const uint4*)g_w2l};
        uint4* d[4] = {(uint4*)(smem + SM_W1H), (uint4*)(smem + SM_W1L),
                       (uint4*)(smem + SM_W2H), (uint4*)(smem + SM_W2L)};
#pragma unroll
        for (int a = 0; a < 4; a++)
            for (int i = tid; i < TILE_B / 16; i += 256) d[a][i] = s[a][i];
    }

    // z tile from aggr -> bf16 hi/lo
#pragma unroll
    for (int it = 0; it < 16; it++) {
        int idx = tid + it * 256;            // 4096 = 128 rows x 32 c4
        int row = idx >> 5, c4 = idx & 31;
        int g = base + row;
        float4 v = make_float4(0.f, 0.f, 0.f, 0.f);
        if (g < N_NODES) v = g_aggr4[(size_t)g * 32 + c4];
        uint2 hv, lv;
        hv.x = splitpair(v.x, v.y, lv.x);
        hv.y = splitpair(v.z, v.w, lv.y);
        *(uint2*)(smem + SM_ZH + row * KSTRB + c4 * 8) = hv;
        *(uint2*)(smem + SM_ZL + row * KSTRB + c4 * 8) = lv;
    }
    __syncthreads();

    // per-lane ldmatrix address constants
    const int aRow = wid * 16 + (lane & 7) + ((lane & 8) ? 8 : 0);
    const uint32_t aByte = (uint32_t)aRow * KSTRB + (((lane & 16) ? 8 : 0) * 2);
    const int bN = (lane & 7) + ((lane & 16) ? 8 : 0);
    const uint32_t bByte = (uint32_t)bN * KSTRB + (((lane & 8) ? 8 : 0) * 2);

    const int g4 = lane >> 2, t4 = lane & 3;
    const int rloc = wid * 16 + g4;          // local rows rloc, rloc+8

    float acc[16][4];
#pragma unroll
    for (int nt = 0; nt < 16; nt++)
#pragma unroll
        for (int i = 0; i < 4; i++) acc[nt][i] = 0.f;

    // GEMM1
    gemm128(sb, SM_ZH, SM_ZL, SM_W1H, SM_W1L, aByte, bByte, acc);

    // epilogue1: h1 = relu(acc + b1) -> bf16 hi/lo back into z tiles (own rows)
    {
        const float* b1s = (const float*)(smem + SM_B1);
#pragma unroll
        for (int nt = 0; nt < 16; nt++) {
            int col = nt * 8 + 2 * t4;
            float v0 = fmaxf(acc[nt][0] + b1s[col],     0.f);
            float v1 = fmaxf(acc[nt][1] + b1s[col + 1], 0.f);
            float v2 = fmaxf(acc[nt][2] + b1s[col],     0.f);
            float v3 = fmaxf(acc[nt][3] + b1s[col + 1], 0.f);
            uint32_t l0, l1;
            uint32_t h0 = splitpair(v0, v1, l0);
            uint32_t h1 = splitpair(v2, v3, l1);
            uint32_t o0 = rloc * KSTRB + col * 2;
            uint32_t o1 = (rloc + 8) * KSTRB + col * 2;
            *(uint32_t*)(smem + SM_ZH + o0) = h0;
            *(uint32_t*)(smem + SM_ZL + o0) = l0;
            *(uint32_t*)(smem + SM_ZH + o1) = h1;
            *(uint32_t*)(smem + SM_ZL + o1) = l1;
            acc[nt][0] = acc[nt][1] = acc[nt][2] = acc[nt][3] = 0.f;
        }
    }
    __syncwarp();

    // GEMM2
    gemm128(sb, SM_ZH, SM_ZL, SM_W2H, SM_W2L, aByte, bByte, acc);

    // epilogue2: out = acc + b2
    {
        const float* b2s = (const float*)(smem + SM_B2);
        int gr = base + rloc;
#pragma unroll
        for (int nt = 0; nt < 16; nt++) {
            int col = nt * 8 + 2 * t4;
            if (gr < N_NODES) {
                float2 v = make_float2(acc[nt][0] + b2s[col],
                                       acc[nt][1] + b2s[col + 1]);
                *(float2*)&out[(size_t)gr * HID + col] = v;
            }
            if (gr + 8 < N_NODES) {
                float2 v = make_float2(acc[nt][2] + b2s[col],
                                       acc[nt][3] + b2s[col + 1]);
                *(float2*)&out[(size_t)(gr + 8) * HID + col] = v;
            }
        }
    }
}

// ---------------------------------------------------------------------------
extern "C" void kernel_launch(void* const* d_in, const int* in_sizes, int n_in,
                              void* d_out, int out_size) {
    const float* x   = (const float*)d_in[0];
    const void*  ei  = d_in[1];
    const void*  ea  = d_in[2];
    const float* emb = (const float*)d_in[3];
    const float* We  = (const float*)d_in[4];
    const float* be  = (const float*)d_in[5];
    const float* W1  = (const float*)d_in[6];
    const float* b1  = (const float*)d_in[7];
    const float* W2  = (const float*)d_in[8];
    const float* b2  = (const float*)d_in[9];
    const float* eps = (const float*)d_in[10];
    float*       out = (float*)d_out;

    cudaFuncSetAttribute(mlp_mma_kernel,
                         cudaFuncAttributeMaxDynamicSharedMemorySize, SM_TOT);

    detect_kernel<<<1, 1>>>((const unsigned*)ei);
    proj_kernel<<<8, 256>>>(emb, We, be);
    wsplit_kernel<<<(2 * 128 * KSTR + 255) / 256, 256>>>(W1, W2);
    init_kernel<<<(N_NODES * HID / 4) / 256, 256>>>((const float4*)x, eps);
    edge_kernel<<<N_EDGES / 8, 256>>>((const float4*)x, ei, ea);
    mlp_mma_kernel<<<(N_NODES + 127) / 128, 256, SM_TOT>>>(b1, b2, out);
}